// round 2
// baseline (speedup 1.0000x reference)
#include <cuda_runtime.h>
#include <math.h>

#define B_  64
#define T_  512
#define N_  128
#define H_  512
#define G_  2048              // 4*H
#define BT_ (B_ * T_)         // 32768
#define NBLK 128              // persistent scan blocks (must all be co-resident)

// -------- device scratch (allocation-free rule: __device__ globals) --------
__device__ float g_xg[(size_t)BT_ * G_];   // 268 MB: X@Wx + b, [bt][4H]
__device__ float g_hs[(size_t)BT_ * H_];   // 67 MB: h history [b][t][H]
__device__ float g_part[4 * B_ * G_];      // split-K partials [ks][b][4H]
__device__ float g_lpart[2048];            // per-block loss partials
__device__ unsigned g_bar_count;
__device__ volatile unsigned g_bar_gen;

// -------- software grid barrier (all NBLK blocks resident) --------
__device__ __forceinline__ void grid_barrier(unsigned nblocks) {
    __threadfence();
    __syncthreads();
    if (threadIdx.x == 0) {
        unsigned gen = g_bar_gen;
        unsigned a = atomicAdd(&g_bar_count, 1u);
        if (a == nblocks - 1) {
            g_bar_count = 0;
            __threadfence();
            g_bar_gen = gen + 1;
        } else {
            while (g_bar_gen == gen) { __nanosleep(64); }
        }
    }
    __syncthreads();
}

// ============================================================
// Kernel A: xg = X @ Wx + b      (M=32768, K=128, N=2048)
// 64x64 block tile, 256 threads, 4x4 micro-tile, K chunked by 64
// ============================================================
__global__ void __launch_bounds__(256) xg_gemm(
    const float* __restrict__ X, const float* __restrict__ Wx,
    const float* __restrict__ bias)
{
    __shared__ float Xs[64][65];   // padded
    __shared__ float Ws[64][64];
    int tid = threadIdx.x;
    int m0 = blockIdx.y * 64;
    int n0 = blockIdx.x * 64;
    int cx = tid & 15, ry = tid >> 4;

    float acc[4][4] = {};
    for (int kc = 0; kc < 128; kc += 64) {
        __syncthreads();
        #pragma unroll
        for (int i = 0; i < 16; i++) {
            int idx = tid + i * 256;         // 0..4095
            int r = idx >> 6, k = idx & 63;
            Xs[r][k] = X[(size_t)(m0 + r) * 128 + kc + k];
        }
        #pragma unroll
        for (int i = 0; i < 16; i++) {
            int idx = tid + i * 256;
            int k = idx >> 6, c = idx & 63;
            Ws[k][c] = Wx[(size_t)(kc + k) * G_ + n0 + c];
        }
        __syncthreads();
        #pragma unroll 8
        for (int k = 0; k < 64; k++) {
            float4 w = *(const float4*)&Ws[k][cx * 4];
            float h0 = Xs[ry * 4 + 0][k];
            float h1 = Xs[ry * 4 + 1][k];
            float h2 = Xs[ry * 4 + 2][k];
            float h3 = Xs[ry * 4 + 3][k];
            acc[0][0] += h0 * w.x; acc[0][1] += h0 * w.y; acc[0][2] += h0 * w.z; acc[0][3] += h0 * w.w;
            acc[1][0] += h1 * w.x; acc[1][1] += h1 * w.y; acc[1][2] += h1 * w.z; acc[1][3] += h1 * w.w;
            acc[2][0] += h2 * w.x; acc[2][1] += h2 * w.y; acc[2][2] += h2 * w.z; acc[2][3] += h2 * w.w;
            acc[3][0] += h3 * w.x; acc[3][1] += h3 * w.y; acc[3][2] += h3 * w.z; acc[3][3] += h3 * w.w;
        }
    }
    float4 bb = *(const float4*)&bias[n0 + cx * 4];
    #pragma unroll
    for (int i = 0; i < 4; i++) {
        int row = m0 + ry * 4 + i;
        float4 o = make_float4(acc[i][0] + bb.x, acc[i][1] + bb.y,
                               acc[i][2] + bb.z, acc[i][3] + bb.w);
        *(float4*)&g_xg[(size_t)row * G_ + n0 + cx * 4] = o;
    }
}

// ============================================================
// Kernel B: persistent LSTM scan. 128 blocks x 256 threads.
//   Phase 1: split-K GEMM h@Wh  (block = colgroup cg (64 cols) x ksplit ks (128 k))
//            Wh slice cached in smem for ALL 512 steps.
//   Phase 2: gate nonlinearity + c/h update (1 cell per thread; c in register)
// ============================================================
#define SMEM_SCAN ((128 * 64 + 128 * 65) * 4)   // Wh_s + h_s = 66048 B

__global__ void __launch_bounds__(256, 1) lstm_scan(const float* __restrict__ Wh)
{
    extern __shared__ float smem[];
    float* Wh_s = smem;              // [128][64]  k-major
    float* h_s  = smem + 128 * 64;   // [128][65]  k-major, padded

    int tid = threadIdx.x;
    int bid = blockIdx.x;
    int cg = bid & 31;               // column group: cols [cg*64, +64)
    int ks = bid >> 5;               // k split: k in [ks*128, +128)
    int n0 = cg * 64;
    int k0 = ks * 128;

    // stage Wh slice once (stays in smem for all 512 steps)
    #pragma unroll
    for (int i = 0; i < 32; i++) {
        int idx = tid + i * 256;             // 0..8191
        int kk = idx >> 6, c = idx & 63;
        Wh_s[kk * 64 + c] = Wh[(size_t)(k0 + kk) * G_ + n0 + c];
    }

    int cx = tid & 15, ry = tid >> 4;        // phase-1 micro-tile coords
    int gt = bid * 256 + tid;                // 0..32767 -> one LSTM cell
    int b_cell = gt >> 9;                    // batch 0..63
    int u_cell = gt & 511;                   // hidden unit 0..511
    float creg = 0.0f;                       // cell state lives in a register

    for (int t = 0; t < T_; t++) {
        // ---- load h(t-1) slice, transposed into smem ----
        __syncthreads();
        if (t == 0) {
            #pragma unroll
            for (int i = 0; i < 32; i++) {
                int idx = tid + i * 256;
                int bb = idx >> 7, kk = idx & 127;
                h_s[kk * 65 + bb] = 0.0f;
            }
        } else {
            #pragma unroll
            for (int i = 0; i < 32; i++) {
                int idx = tid + i * 256;
                int bb = idx >> 7, kk = idx & 127;
                h_s[kk * 65 + bb] = g_hs[((size_t)(bb * T_ + (t - 1))) * H_ + k0 + kk];
            }
        }
        __syncthreads();

        // ---- phase 1: partial GEMM: 64 batches x 64 cols, K=128 ----
        float acc[4][4] = {};
        #pragma unroll 4
        for (int kk = 0; kk < 128; kk++) {
            float4 w = *(const float4*)&Wh_s[kk * 64 + cx * 4];
            float h0 = h_s[kk * 65 + ry * 4 + 0];
            float h1 = h_s[kk * 65 + ry * 4 + 1];
            float h2 = h_s[kk * 65 + ry * 4 + 2];
            float h3 = h_s[kk * 65 + ry * 4 + 3];
            acc[0][0] += h0 * w.x; acc[0][1] += h0 * w.y; acc[0][2] += h0 * w.z; acc[0][3] += h0 * w.w;
            acc[1][0] += h1 * w.x; acc[1][1] += h1 * w.y; acc[1][2] += h1 * w.z; acc[1][3] += h1 * w.w;
            acc[2][0] += h2 * w.x; acc[2][1] += h2 * w.y; acc[2][2] += h2 * w.z; acc[2][3] += h2 * w.w;
            acc[3][0] += h3 * w.x; acc[3][1] += h3 * w.y; acc[3][2] += h3 * w.z; acc[3][3] += h3 * w.w;
        }
        #pragma unroll
        for (int i = 0; i < 4; i++) {
            int row = ry * 4 + i;  // batch row
            *(float4*)&g_part[(size_t)(ks * B_ + row) * G_ + n0 + cx * 4] =
                make_float4(acc[i][0], acc[i][1], acc[i][2], acc[i][3]);
        }
        grid_barrier(NBLK);

        // ---- phase 2: sum partials + gates + state update (1 cell/thread) ----
        {
            size_t xoff = ((size_t)(b_cell * T_ + t)) * G_;
            float s[4];
            #pragma unroll
            for (int gi = 0; gi < 4; gi++) {
                int col = gi * H_ + u_cell;
                float v = g_xg[xoff + col];
                v += g_part[(size_t)(0 * B_ + b_cell) * G_ + col];
                v += g_part[(size_t)(1 * B_ + b_cell) * G_ + col];
                v += g_part[(size_t)(2 * B_ + b_cell) * G_ + col];
                v += g_part[(size_t)(3 * B_ + b_cell) * G_ + col];
                s[gi] = v;
            }
            float ig = 1.0f / (1.0f + expf(-s[0]));
            float jg = tanhf(s[1]);
            float fg = 1.0f / (1.0f + expf(-(s[2] + 1.0f)));  // forget_bias = 1
            float og = 1.0f / (1.0f + expf(-s[3]));
            creg = fg * creg + ig * jg;
            float h = og * tanhf(creg);
            g_hs[((size_t)(b_cell * T_ + t)) * H_ + u_cell] = h;
        }
        grid_barrier(NBLK);
    }
}

// ============================================================
// Kernel C: logits = sigmoid(hs@Wd + bd); per-block partial of sum((Y-logits)^2)
// block = 16 bt-rows x 128 cols; 256 threads; thread = 8 rows x 1 col
// ============================================================
__global__ void __launch_bounds__(256) out_loss(
    const float* __restrict__ Wd, const float* __restrict__ bd,
    const float* __restrict__ Y)
{
    __shared__ float h_s[512][20];   // [k][r], padded: 16B-aligned float4 at r=0/8, low conflicts
    __shared__ float red[8];
    int tid = threadIdx.x;
    int row0 = blockIdx.x * 16;

    #pragma unroll
    for (int i = 0; i < 32; i++) {
        int idx = tid + i * 256;             // 0..8191
        int r = idx >> 9, k = idx & 511;
        h_s[k][r] = g_hs[(size_t)(row0 + r) * H_ + k];
    }
    __syncthreads();

    int c = tid & 127;
    int rh = tid >> 7;                       // 0..1 -> rows rh*8..+7
    float acc[8] = {};
    #pragma unroll 4
    for (int k = 0; k < 512; k++) {
        float w = Wd[(size_t)k * N_ + c];
        float4 a = *(const float4*)&h_s[k][rh * 8];
        float4 b4 = *(const float4*)&h_s[k][rh * 8 + 4];
        acc[0] += a.x * w;  acc[1] += a.y * w;  acc[2] += a.z * w;  acc[3] += a.w * w;
        acc[4] += b4.x * w; acc[5] += b4.y * w; acc[6] += b4.z * w; acc[7] += b4.w * w;
    }
    float bdc = bd[c];
    float lsum = 0.0f;
    #pragma unroll
    for (int i = 0; i < 8; i++) {
        int row = row0 + rh * 8 + i;
        float logit = 1.0f / (1.0f + expf(-(acc[i] + bdc)));
        float d = Y[(size_t)row * N_ + c] - logit;
        lsum += d * d;
    }
    #pragma unroll
    for (int o = 16; o; o >>= 1) lsum += __shfl_xor_sync(0xFFFFFFFFu, lsum, o);
    if ((tid & 31) == 0) red[tid >> 5] = lsum;
    __syncthreads();
    if (tid == 0) {
        float s = 0.0f;
        #pragma unroll
        for (int i = 0; i < 8; i++) s += red[i];
        g_lpart[blockIdx.x] = s;
    }
}

// ============================================================
// Kernel D: final deterministic reduction -> loss scalar
// ============================================================
__global__ void finalize(float* __restrict__ out)
{
    __shared__ float red[8];
    int tid = threadIdx.x;
    float s = 0.0f;
    for (int i = tid; i < 2048; i += 256) s += g_lpart[i];
    #pragma unroll
    for (int o = 16; o; o >>= 1) s += __shfl_xor_sync(0xFFFFFFFFu, s, o);
    if ((tid & 31) == 0) red[tid >> 5] = s;
    __syncthreads();
    if (tid == 0) {
        float t = 0.0f;
        #pragma unroll
        for (int i = 0; i < 8; i++) t += red[i];
        out[0] = t * (100.0f / ((float)B_ * (float)T_ * (float)N_));
    }
}

// ============================================================
extern "C" void kernel_launch(void* const* d_in, const int* in_sizes, int n_in,
                              void* d_out, int out_size)
{
    const float* X  = (const float*)d_in[0];
    const float* Y  = (const float*)d_in[1];
    const float* Wx = (const float*)d_in[2];
    const float* Wh = (const float*)d_in[3];
    const float* b  = (const float*)d_in[4];
    const float* Wd = (const float*)d_in[5];
    const float* bd = (const float*)d_in[6];
    (void)in_sizes; (void)n_in; (void)out_size;

    cudaFuncSetAttribute(lstm_scan, cudaFuncAttributeMaxDynamicSharedMemorySize, SMEM_SCAN);

    dim3 gA(G_ / 64, BT_ / 64);                 // 32 x 512
    xg_gemm<<<gA, 256>>>(X, Wx, b);
    lstm_scan<<<NBLK, 256, SMEM_SCAN>>>(Wh);
    out_loss<<<BT_ / 16, 256>>>(Wd, bd, Y);     // 2048 blocks
    finalize<<<1, 256>>>((float*)d_out);
}